// round 1
// baseline (speedup 1.0000x reference)
#include <cuda_runtime.h>
#include <cstdint>

#define DIM 4096
#define NITER 20
#define RS 32                       // row splits for the column pass
#define ROWS_PER_SPLIT (DIM / RS)   // 128

// Scratch (static __device__ arrays are the allowed scratch mechanism)
__device__ float g_E[(size_t)DIM * DIM];   // 64 MB: E = exp((logits + gumbel)/T)
__device__ float g_u[DIM];                 // exp(-c_j)
__device__ float g_v[DIM];                 // exp(-r_i)
__device__ float g_part[RS * DIM];         // column-pass partials

// Accurate-enough gumbel->exp transform.
// g = -log(-log(noise+eps)+eps);  returns exp(logit + g)
__device__ __forceinline__ float gumbel_exp(float logit, float noise) {
    const float EPS = 1e-10f;
    float y = noise + EPS;
    float u = y - 1.0f;
    float w;  // w = -log(y)
    if (fabsf(u) < 0.125f) {
        // log1p(u)/u polynomial through u^6 term; truncation rel err <= 6e-8
        float p = 1.0f + u * (-0.5f + u * (0.33333333f + u * (-0.25f
                   + u * (0.2f + u * (-0.16666667f + u * 0.14285715f)))));
        w = -(u * p);
    } else {
        w = -__logf(y);
    }
    float g = -__logf(w + EPS);
    return __expf(logit + g);
}

__global__ __launch_bounds__(256)
void setup_kernel(const float* __restrict__ logits, const float* __restrict__ noise) {
    size_t t = (size_t)blockIdx.x * 256 + threadIdx.x;
    if (t < DIM) g_u[t] = 1.0f;          // init column scaling
    size_t i = t * 4;
    float4 l = *reinterpret_cast<const float4*>(logits + i);
    float4 n = *reinterpret_cast<const float4*>(noise + i);
    float4 e;
    e.x = gumbel_exp(l.x, n.x);
    e.y = gumbel_exp(l.y, n.y);
    e.z = gumbel_exp(l.z, n.z);
    e.w = gumbel_exp(l.w, n.w);
    *reinterpret_cast<float4*>(g_E + i) = e;
}

// Row pass: v_i = 1 / sum_j E[i,j] * u_j.  One block per row.
__global__ __launch_bounds__(256)
void row_kernel() {
    int row = blockIdx.x;
    const float4* E4 = reinterpret_cast<const float4*>(g_E + (size_t)row * DIM);
    const float4* u4 = reinterpret_cast<const float4*>(g_u);
    float s = 0.0f;
    #pragma unroll
    for (int j = threadIdx.x; j < DIM / 4; j += 256) {
        float4 e = E4[j];
        float4 uu = u4[j];
        s = fmaf(e.x, uu.x, s);
        s = fmaf(e.y, uu.y, s);
        s = fmaf(e.z, uu.z, s);
        s = fmaf(e.w, uu.w, s);
    }
    #pragma unroll
    for (int o = 16; o; o >>= 1) s += __shfl_down_sync(0xffffffffu, s, o);
    __shared__ float sh[8];
    int lane = threadIdx.x & 31, wid = threadIdx.x >> 5;
    if (lane == 0) sh[wid] = s;
    __syncthreads();
    if (threadIdx.x == 0) {
        float tot = sh[0];
        #pragma unroll
        for (int k = 1; k < 8; k++) tot += sh[k];
        g_v[row] = 1.0f / tot;
    }
}

// Column pass (partials): each block owns 256 columns x 128 rows.
__global__ __launch_bounds__(256)
void col_kernel() {
    int col = blockIdx.x * 256 + threadIdx.x;
    int r0 = blockIdx.y * ROWS_PER_SPLIT;
    float s = 0.0f;
    #pragma unroll 8
    for (int r = r0; r < r0 + ROWS_PER_SPLIT; ++r) {
        s = fmaf(g_E[(size_t)r * DIM + col], g_v[r], s);
    }
    g_part[blockIdx.y * DIM + col] = s;
}

// Combine partials: u_j = 1 / sum_k part[k][j]
__global__ __launch_bounds__(256)
void comb_kernel() {
    int col = blockIdx.x * 256 + threadIdx.x;
    float s = 0.0f;
    #pragma unroll
    for (int k = 0; k < RS; k++) s += g_part[k * DIM + col];
    g_u[col] = 1.0f / s;
}

// Output: out[i,j] = E[i,j] * v_i * u_j
__global__ __launch_bounds__(256)
void final_kernel(float* __restrict__ out) {
    size_t t = (size_t)blockIdx.x * 256 + threadIdx.x;
    int row = (int)(t >> 10);       // 1024 float4 per row
    int jc  = (int)(t & 1023);
    float4 e = reinterpret_cast<const float4*>(g_E)[t];
    float4 uu = reinterpret_cast<const float4*>(g_u)[jc];
    float v = g_v[row];
    float4 o;
    o.x = e.x * v * uu.x;
    o.y = e.y * v * uu.y;
    o.z = e.z * v * uu.z;
    o.w = e.w * v * uu.w;
    reinterpret_cast<float4*>(out)[t] = o;
}

extern "C" void kernel_launch(void* const* d_in, const int* in_sizes, int n_in,
                              void* d_out, int out_size) {
    const float* logits = (const float*)d_in[0];
    const float* noise  = (const float*)d_in[1];
    float* out = (float*)d_out;

    const int ELEM_BLOCKS = (DIM * DIM / 4) / 256;   // 16384

    setup_kernel<<<ELEM_BLOCKS, 256>>>(logits, noise);
    for (int it = 0; it < NITER; ++it) {
        row_kernel<<<DIM, 256>>>();
        col_kernel<<<dim3(DIM / 256, RS), 256>>>();
        comb_kernel<<<DIM / 256, 256>>>();
    }
    final_kernel<<<ELEM_BLOCKS, 256>>>(out);
}

// round 2
// speedup vs baseline: 1.1183x; 1.1183x over previous
#include <cuda_runtime.h>
#include <cstdint>

#define DIM   4096
#define NITER 20
#define NBLK  148
#define NTHR  1024

// Scratch (static __device__ arrays are the allowed scratch mechanism)
__device__ float g_E[(size_t)DIM * DIM];   // 64 MB: E = exp(logits + gumbel)
__device__ float g_usum[2][DIM];           // ping-pong column-sum accumulators
__device__ float g_v[DIM];                 // 1 / rowsum
__device__ unsigned int g_bar;             // grid barrier counter

// g = -log(-log(noise+eps)+eps);  returns exp(logit + g)
__device__ __forceinline__ float gumbel_exp(float logit, float noise) {
    const float EPS = 1e-10f;
    float y = noise + EPS;
    float u = y - 1.0f;
    float w;  // w = -log(y)
    if (fabsf(u) < 0.125f) {
        // log1p(u)/u polynomial; keeps relative accuracy where -log(y) ~ 0
        float p = 1.0f + u * (-0.5f + u * (0.33333333f + u * (-0.25f
                   + u * (0.2f + u * (-0.16666667f + u * 0.14285715f)))));
        w = -(u * p);
    } else {
        w = -__logf(y);
    }
    float g = -__logf(w + EPS);
    return __expf(logit + g);
}

__global__ void reset_kernel() { g_bar = 0u; }

__global__ __launch_bounds__(NTHR, 1)
void sinkhorn_kernel(const float* __restrict__ logits,
                     const float* __restrict__ noise,
                     float* __restrict__ out) {
    __shared__ float u_sm[DIM];    // 16 KB: inverted column scalings
    __shared__ float v_sm[32];     // per-block row scalings for col pass

    const int tid  = threadIdx.x;
    const int bid  = blockIdx.x;
    const int lane = tid & 31;
    const int wid  = tid >> 5;
    unsigned epoch = 0;

    // software grid barrier: all 148 blocks are resident (single wave)
    auto gsync = [&]() {
        __syncthreads();
        __threadfence();                     // release all prior writes
        ++epoch;
        if (tid == 0) {
            atomicAdd(&g_bar, 1u);
            const unsigned target = epoch * NBLK;
            while (*((volatile unsigned*)&g_bar) < target) { }
            __threadfence();                 // acquire
        }
        __syncthreads();
    };

    // ---------------- setup: E = exp(logits + gumbel), init usum ----------------
    {
        const float4* l4 = reinterpret_cast<const float4*>(logits);
        const float4* n4 = reinterpret_cast<const float4*>(noise);
        float4*       e4 = reinterpret_cast<float4*>(g_E);
        const size_t total = (size_t)DIM * DIM / 4;
        for (size_t i = (size_t)bid * NTHR + tid; i < total; i += (size_t)NBLK * NTHR) {
            float4 l = l4[i], n = n4[i], e;
            e.x = gumbel_exp(l.x, n.x);
            e.y = gumbel_exp(l.y, n.y);
            e.z = gumbel_exp(l.z, n.z);
            e.w = gumbel_exp(l.w, n.w);
            e4[i] = e;
        }
        if (bid == 0) {
            for (int j = tid; j < DIM; j += NTHR) {
                g_usum[0][j] = 1.0f;   // u starts at 1
                g_usum[1][j] = 0.0f;   // first accumulation target
            }
        }
    }
    gsync();

    // ---------------- 20 Sinkhorn iterations ----------------
    for (int it = 0; it < NITER; ++it) {
        // ---- row pass: v_i = 1 / sum_j E[i,j] * u_j ----
        {
            const float* us = g_usum[it & 1];
            for (int j = tid; j < DIM; j += NTHR) u_sm[j] = 1.0f / us[j];
            // zero next accumulator slice (safe: last read 2 barriers ago)
            {
                float* un = g_usum[(it + 1) & 1];
                int j = bid * 28 + tid;
                if (tid < 28 && j < DIM) un[j] = 0.0f;
            }
            __syncthreads();

            int row = wid * NBLK + bid;          // spread rows for block balance
            if (row < DIM) {
                const float4* E4 = reinterpret_cast<const float4*>(g_E + (size_t)row * DIM);
                const float4* u4 = reinterpret_cast<const float4*>(u_sm);
                float s = 0.0f;
                #pragma unroll 8
                for (int j = lane; j < DIM / 4; j += 32) {
                    float4 e = E4[j], uu = u4[j];
                    s = fmaf(e.x, uu.x, s);
                    s = fmaf(e.y, uu.y, s);
                    s = fmaf(e.z, uu.z, s);
                    s = fmaf(e.w, uu.w, s);
                }
                #pragma unroll
                for (int o = 16; o; o >>= 1) s += __shfl_down_sync(0xffffffffu, s, o);
                if (lane == 0) g_v[row] = 1.0f / s;
            }
        }
        gsync();

        // ---- col pass: usum_next[j] += sum_i E[i,j] * v_i  (block owns spread rows) ----
        {
            const int nr = (DIM - bid + NBLK - 1) / NBLK;   // 27 or 28
            if (tid < nr) v_sm[tid] = g_v[tid * NBLK + bid];
            __syncthreads();

            float* un = g_usum[(it + 1) & 1];
            float acc0 = 0.f, acc1 = 0.f, acc2 = 0.f, acc3 = 0.f;
            for (int k = 0; k < nr; ++k) {
                const float* Erow = g_E + (size_t)(k * NBLK + bid) * DIM + tid;
                float vv = v_sm[k];
                acc0 = fmaf(Erow[0],    vv, acc0);
                acc1 = fmaf(Erow[1024], vv, acc1);
                acc2 = fmaf(Erow[2048], vv, acc2);
                acc3 = fmaf(Erow[3072], vv, acc3);
            }
            atomicAdd(&un[tid],        acc0);
            atomicAdd(&un[1024 + tid], acc1);
            atomicAdd(&un[2048 + tid], acc2);
            atomicAdd(&un[3072 + tid], acc3);
        }
        gsync();
    }

    // ---------------- final: out[i,j] = E[i,j] * v_i * u_j ----------------
    {
        const float* us = g_usum[NITER & 1];    // usum[0] after 20 iterations
        for (int j = tid; j < DIM; j += NTHR) u_sm[j] = 1.0f / us[j];
        __syncthreads();

        int row = wid * NBLK + bid;
        if (row < DIM) {
            const float v = g_v[row];
            const float4* E4 = reinterpret_cast<const float4*>(g_E + (size_t)row * DIM);
            const float4* u4 = reinterpret_cast<const float4*>(u_sm);
            float4* o4 = reinterpret_cast<float4*>(out + (size_t)row * DIM);
            #pragma unroll 4
            for (int j = lane; j < DIM / 4; j += 32) {
                float4 e = E4[j], uu = u4[j], o;
                o.x = e.x * v * uu.x;
                o.y = e.y * v * uu.y;
                o.z = e.z * v * uu.z;
                o.w = e.w * v * uu.w;
                o4[j] = o;
            }
        }
    }
}

extern "C" void kernel_launch(void* const* d_in, const int* in_sizes, int n_in,
                              void* d_out, int out_size) {
    const float* logits = (const float*)d_in[0];
    const float* noise  = (const float*)d_in[1];
    float* out = (float*)d_out;

    reset_kernel<<<1, 1>>>();
    sinkhorn_kernel<<<NBLK, NTHR>>>(logits, noise, out);
}

// round 3
// speedup vs baseline: 1.1556x; 1.0334x over previous
#include <cuda_runtime.h>
#include <cstdint>

#define DIM   4096
#define NITER 20
#define NBLK  148
#define NTHR  1024
#define CROWS 12                    // rows of E cached in smem per block
#define SMEM_FLOATS (CROWS * DIM + DIM)          // cached rows + u_inv
#define SMEM_BYTES  (SMEM_FLOATS * sizeof(float))  // 212,992 B

// Scratch (static __device__ arrays are the allowed scratch mechanism)
__device__ float g_E[(size_t)DIM * DIM];   // 64 MB: E = exp(logits + gumbel)
__device__ float g_usum[2][DIM];           // ping-pong column-sum accumulators
__device__ float g_v[DIM];                 // 1 / rowsum
__device__ unsigned int g_bar;             // grid barrier counter

// g = -log(-log(noise+eps)+eps);  returns exp(logit + g)
__device__ __forceinline__ float gumbel_exp(float logit, float noise) {
    const float EPS = 1e-10f;
    float y = noise + EPS;
    float u = y - 1.0f;
    float w;  // w = -log(y)
    if (fabsf(u) < 0.125f) {
        float p = 1.0f + u * (-0.5f + u * (0.33333333f + u * (-0.25f
                   + u * (0.2f + u * (-0.16666667f + u * 0.14285715f)))));
        w = -(u * p);
    } else {
        w = -__logf(y);
    }
    float g = -__logf(w + EPS);
    return __expf(logit + g);
}

__global__ void reset_kernel() { g_bar = 0u; }

__device__ __forceinline__ float row_dot(const float4* __restrict__ E4,
                                         const float4* __restrict__ u4, int lane) {
    float s = 0.0f;
    #pragma unroll 8
    for (int j = lane; j < DIM / 4; j += 32) {
        float4 e = E4[j], uu = u4[j];
        s = fmaf(e.x, uu.x, s);
        s = fmaf(e.y, uu.y, s);
        s = fmaf(e.z, uu.z, s);
        s = fmaf(e.w, uu.w, s);
    }
    #pragma unroll
    for (int o = 16; o; o >>= 1) s += __shfl_down_sync(0xffffffffu, s, o);
    return s;
}

__global__ __launch_bounds__(NTHR, 1)
void sinkhorn_kernel(const float* __restrict__ logits,
                     const float* __restrict__ noise,
                     float* __restrict__ out) {
    extern __shared__ float sm[];              // [CROWS*DIM] cached rows | [DIM] u_inv
    float* u_inv = sm + CROWS * DIM;

    const int tid  = threadIdx.x;
    const int bid  = blockIdx.x;
    const int lane = tid & 31;
    const int wid  = tid >> 5;
    const int nr   = (DIM - bid + NBLK - 1) / NBLK;   // 28 (bid<100) or 27
    unsigned epoch = 0;

    // software grid barrier (148 blocks = single wave)
    auto gsync = [&]() {
        __syncthreads();
        __threadfence();
        ++epoch;
        if (tid == 0) {
            atomicAdd(&g_bar, 1u);
            const unsigned target = epoch * NBLK;
            while (*((volatile unsigned*)&g_bar) < target) { }
            __threadfence();
        }
        __syncthreads();
    };

    // ---------------- setup: E = exp(logits+gumbel); cache CROWS rows in smem ----
    for (int k = 0; k < nr; ++k) {
        const int row = k * NBLK + bid;
        const float4 l = reinterpret_cast<const float4*>(logits + (size_t)row * DIM)[tid];
        const float4 n = reinterpret_cast<const float4*>(noise  + (size_t)row * DIM)[tid];
        float4 e;
        e.x = gumbel_exp(l.x, n.x);
        e.y = gumbel_exp(l.y, n.y);
        e.z = gumbel_exp(l.z, n.z);
        e.w = gumbel_exp(l.w, n.w);
        reinterpret_cast<float4*>(g_E + (size_t)row * DIM)[tid] = e;
        if (k < CROWS) reinterpret_cast<float4*>(sm + k * DIM)[tid] = e;
    }
    if (bid == 0) {
        for (int j = tid; j < DIM; j += NTHR) {
            g_usum[0][j] = 1.0f;
            g_usum[1][j] = 0.0f;
        }
    }
    gsync();

    // ---------------- 20 Sinkhorn iterations ----------------
    for (int it = 0; it < NITER; ++it) {
        // ---- row pass: v_i = 1 / sum_j E[i,j] * u_j ----
        {
            const float* us = g_usum[it & 1];
            for (int j = tid; j < DIM; j += NTHR) u_inv[j] = 1.0f / us[j];
            {   // zero next accumulator slice (last read 2 barriers ago)
                float* un = g_usum[(it + 1) & 1];
                int j = bid * 28 + tid;
                if (tid < 28 && j < DIM) un[j] = 0.0f;
            }
            __syncthreads();

            const int k = wid;                   // local row index
            if (k < nr) {
                const float4* u4 = reinterpret_cast<const float4*>(u_inv);
                float s;
                if (k < CROWS)
                    s = row_dot(reinterpret_cast<const float4*>(sm + k * DIM), u4, lane);
                else
                    s = row_dot(reinterpret_cast<const float4*>(g_E + (size_t)(k * NBLK + bid) * DIM), u4, lane);
                if (lane == 0) g_v[k * NBLK + bid] = 1.0f / s;
            }
        }
        gsync();

        // ---- col pass: usum_next[j] += sum_i E[i,j] * v_i ----
        {
            float* un = g_usum[(it + 1) & 1];
            float a0 = 0.f, a1 = 0.f, a2 = 0.f, a3 = 0.f;
            #pragma unroll
            for (int k = 0; k < CROWS; ++k) {
                const float vv = g_v[k * NBLK + bid];
                const float* Er = sm + k * DIM + tid;
                a0 = fmaf(Er[0],    vv, a0);
                a1 = fmaf(Er[1024], vv, a1);
                a2 = fmaf(Er[2048], vv, a2);
                a3 = fmaf(Er[3072], vv, a3);
            }
            for (int k = CROWS; k < nr; ++k) {
                const float vv = g_v[k * NBLK + bid];
                const float* Er = g_E + (size_t)(k * NBLK + bid) * DIM + tid;
                a0 = fmaf(Er[0],    vv, a0);
                a1 = fmaf(Er[1024], vv, a1);
                a2 = fmaf(Er[2048], vv, a2);
                a3 = fmaf(Er[3072], vv, a3);
            }
            atomicAdd(&un[tid],        a0);
            atomicAdd(&un[1024 + tid], a1);
            atomicAdd(&un[2048 + tid], a2);
            atomicAdd(&un[3072 + tid], a3);
        }
        gsync();
    }

    // ---------------- final: out[i,j] = E[i,j] * v_i * u_j ----------------
    {
        const float* us = g_usum[NITER & 1];
        for (int j = tid; j < DIM; j += NTHR) u_inv[j] = 1.0f / us[j];
        __syncthreads();

        const int k = wid;
        if (k < nr) {
            const int row = k * NBLK + bid;
            const float v = g_v[row];
            const float4* u4 = reinterpret_cast<const float4*>(u_inv);
            float4* o4 = reinterpret_cast<float4*>(out + (size_t)row * DIM);
            if (k < CROWS) {
                const float4* E4 = reinterpret_cast<const float4*>(sm + k * DIM);
                #pragma unroll 4
                for (int j = lane; j < DIM / 4; j += 32) {
                    float4 e = E4[j], uu = u4[j], o;
                    o.x = e.x * v * uu.x;
                    o.y = e.y * v * uu.y;
                    o.z = e.z * v * uu.z;
                    o.w = e.w * v * uu.w;
                    o4[j] = o;
                }
            } else {
                const float4* E4 = reinterpret_cast<const float4*>(g_E + (size_t)row * DIM);
                #pragma unroll 4
                for (int j = lane; j < DIM / 4; j += 32) {
                    float4 e = E4[j], uu = u4[j], o;
                    o.x = e.x * v * uu.x;
                    o.y = e.y * v * uu.y;
                    o.z = e.z * v * uu.z;
                    o.w = e.w * v * uu.w;
                    o4[j] = o;
                }
            }
        }
    }
}

extern "C" void kernel_launch(void* const* d_in, const int* in_sizes, int n_in,
                              void* d_out, int out_size) {
    const float* logits = (const float*)d_in[0];
    const float* noise  = (const float*)d_in[1];
    float* out = (float*)d_out;

    static bool configured = false;
    if (!configured) {
        cudaFuncSetAttribute(sinkhorn_kernel,
                             cudaFuncAttributeMaxDynamicSharedMemorySize, SMEM_BYTES);
        configured = true;
    }

    reset_kernel<<<1, 1>>>();
    sinkhorn_kernel<<<NBLK, NTHR, SMEM_BYTES>>>(logits, noise, out);
}